// round 2
// baseline (speedup 1.0000x reference)
#include <cuda_runtime.h>
#include <cstdint>

// ---------------------------------------------------------------------------
// AggregationFusion: gather + concat + LN -> Linear(1024,1024)+SiLU -> LN ->
//                    Linear(1024,512)+SiLU
// N=100000 rows, F=512 (2F=1024), M=16384 super-nodes.
// ---------------------------------------------------------------------------

#define MAX_N 100000
#define TWOF  1024
#define FDIM  512
#define LN_EPS 1e-5f

// Scratch (allocation-free rule: __device__ globals)
__device__ float g_X[(size_t)MAX_N * TWOF];   // LN1 output / LN2 output (reused)
__device__ float g_H[(size_t)MAX_N * TWOF];   // GEMM1 output
__device__ int   g_is64;                      // 1 if comps/aggr_comps are int64

// ---------------------------------------------------------------------------
// dtype detection: int64 little-endian positives < 2^31 have zero odd words.
// ---------------------------------------------------------------------------
__global__ void detect_i64_kernel(const int* __restrict__ comps_words) {
    if (threadIdx.x == 0) {
        int z = 1;
        #pragma unroll
        for (int i = 1; i < 16; i += 2)
            if (comps_words[i] != 0) z = 0;
        g_is64 = z;
    }
}

// ---------------------------------------------------------------------------
// block reduction (256 threads)
// ---------------------------------------------------------------------------
__device__ __forceinline__ float block_reduce_sum_256(float v, float* sbuf) {
    __syncthreads();  // protect sbuf reuse across consecutive calls
    #pragma unroll
    for (int o = 16; o > 0; o >>= 1) v += __shfl_xor_sync(0xffffffffu, v, o);
    int w = threadIdx.x >> 5, l = threadIdx.x & 31;
    if (l == 0) sbuf[w] = v;
    __syncthreads();
    if (w == 0) {
        v = (l < 8) ? sbuf[l] : 0.0f;
        #pragma unroll
        for (int o = 4; o > 0; o >>= 1) v += __shfl_xor_sync(0xffffffffu, v, o);
        if (l == 0) sbuf[0] = v;
    }
    __syncthreads();
    return sbuf[0];
}

__device__ __forceinline__ float silu_f(float x) {
    return x * (1.0f / (1.0f + __expf(-x)));
}

// ---------------------------------------------------------------------------
// Kernel 1: gather (binary search) + concat + LayerNorm1 -> g_X  [N,1024]
// one block (256 threads) per row; each thread owns one float4 of the row.
// ---------------------------------------------------------------------------
__global__ void gather_ln1_kernel(const float* __restrict__ nodes,
                                  const void* __restrict__ comps,
                                  const float* __restrict__ aggr_nodes,
                                  const void* __restrict__ aggr_comps,
                                  const float* __restrict__ ln_g,
                                  const float* __restrict__ ln_b,
                                  int N, int M) {
    int row = blockIdx.x;
    if (row >= N) return;
    int tid = threadIdx.x;

    __shared__ float red[8];
    __shared__ int s_idx;

    if (tid == 0) {
        int is64 = g_is64;
        long long key = is64 ? ((const long long*)comps)[row]
                             : (long long)((const int*)comps)[row];
        int lo = 0, hi = M;  // lower_bound (searchsorted side='left')
        while (lo < hi) {
            int mid = (lo + hi) >> 1;
            long long am = is64 ? ((const long long*)aggr_comps)[mid]
                                : (long long)((const int*)aggr_comps)[mid];
            if (am < key) lo = mid + 1; else hi = mid;
        }
        if (lo >= M) lo = M - 1;
        s_idx = lo;
    }
    __syncthreads();
    int idx = s_idx;

    // combined[tid*4 .. tid*4+3]: first half from nodes, second from gathered aggr
    float4 v;
    if (tid < 128)
        v = ((const float4*)(nodes + (size_t)row * FDIM))[tid];
    else
        v = ((const float4*)(aggr_nodes + (size_t)idx * FDIM))[tid - 128];

    float sum = v.x + v.y + v.z + v.w;
    sum = block_reduce_sum_256(sum, red);
    float mu = sum * (1.0f / (float)TWOF);

    float dx = v.x - mu, dy = v.y - mu, dz = v.z - mu, dw = v.w - mu;
    float sq = dx * dx + dy * dy + dz * dz + dw * dw;
    sq = block_reduce_sum_256(sq, red);
    float rstd = rsqrtf(sq * (1.0f / (float)TWOF) + LN_EPS);

    float4 gg = ((const float4*)ln_g)[tid];
    float4 bb = ((const float4*)ln_b)[tid];
    float4 o;
    o.x = dx * rstd * gg.x + bb.x;
    o.y = dy * rstd * gg.y + bb.y;
    o.z = dz * rstd * gg.z + bb.z;
    o.w = dw * rstd * gg.w + bb.w;
    ((float4*)(g_X + (size_t)row * TWOF))[tid] = o;
}

// ---------------------------------------------------------------------------
// Kernel 3: LayerNorm2 over g_H rows -> g_X (reuse)
// ---------------------------------------------------------------------------
__global__ void ln2_kernel(const float* __restrict__ ln_g,
                           const float* __restrict__ ln_b,
                           int N) {
    int row = blockIdx.x;
    if (row >= N) return;
    int tid = threadIdx.x;
    __shared__ float red[8];

    float4 v = ((const float4*)(g_H + (size_t)row * TWOF))[tid];
    float sum = v.x + v.y + v.z + v.w;
    sum = block_reduce_sum_256(sum, red);
    float mu = sum * (1.0f / (float)TWOF);

    float dx = v.x - mu, dy = v.y - mu, dz = v.z - mu, dw = v.w - mu;
    float sq = dx * dx + dy * dy + dz * dz + dw * dw;
    sq = block_reduce_sum_256(sq, red);
    float rstd = rsqrtf(sq * (1.0f / (float)TWOF) + LN_EPS);

    float4 gg = ((const float4*)ln_g)[tid];
    float4 bb = ((const float4*)ln_b)[tid];
    float4 o;
    o.x = dx * rstd * gg.x + bb.x;
    o.y = dy * rstd * gg.y + bb.y;
    o.z = dz * rstd * gg.z + bb.z;
    o.w = dw * rstd * gg.w + bb.w;
    ((float4*)(g_X + (size_t)row * TWOF))[tid] = o;
}

// ---------------------------------------------------------------------------
// GEMM: C[Nrows, Ncols] = silu(A[Nrows,1024] @ W[1024,Ncols] + bias)
// 128x128 block tile, BK=16, 256 threads, 8x8 per thread, smem double buffer.
// ---------------------------------------------------------------------------
__global__ __launch_bounds__(256, 2)
void gemm_bias_silu_kernel(const float* __restrict__ A,
                           const float* __restrict__ W,
                           const float* __restrict__ bias,
                           float* __restrict__ C,
                           int Nrows, int Ncols) {
    const int K = 1024;
    const int KT = K / 16;

    __shared__ float As[2][16][128];
    __shared__ float Bs[2][16][128];

    int tid = threadIdx.x;
    int tx = tid & 15;         // output col group
    int ty = tid >> 4;         // output row group
    int rowBase = blockIdx.y * 128;
    int colBase = blockIdx.x * 128;

    float acc[8][8];
    #pragma unroll
    for (int i = 0; i < 8; i++)
        #pragma unroll
        for (int j = 0; j < 8; j++) acc[i][j] = 0.0f;

    float4 aReg[2], bReg[2];

    // ---- prologue: load tile 0 ----
    #pragma unroll
    for (int i = 0; i < 2; i++) {
        int id = tid + i * 256;
        int r = id >> 2, c4 = id & 3;
        int gr = rowBase + r;
        aReg[i] = (gr < Nrows)
            ? *(const float4*)(A + (size_t)gr * K + c4 * 4)
            : make_float4(0.f, 0.f, 0.f, 0.f);
        int br = id >> 5, bc4 = id & 31;
        bReg[i] = *(const float4*)(W + (size_t)br * Ncols + colBase + bc4 * 4);
    }
    #pragma unroll
    for (int i = 0; i < 2; i++) {
        int id = tid + i * 256;
        int r = id >> 2, c4 = id & 3;
        As[0][c4 * 4 + 0][r] = aReg[i].x;
        As[0][c4 * 4 + 1][r] = aReg[i].y;
        As[0][c4 * 4 + 2][r] = aReg[i].z;
        As[0][c4 * 4 + 3][r] = aReg[i].w;
        int br = id >> 5, bc4 = id & 31;
        *(float4*)&Bs[0][br][bc4 * 4] = bReg[i];
    }
    __syncthreads();

    int buf = 0;
    for (int kt = 0; kt < KT; kt++) {
        // prefetch next tile into registers
        if (kt + 1 < KT) {
            int k0 = (kt + 1) * 16;
            #pragma unroll
            for (int i = 0; i < 2; i++) {
                int id = tid + i * 256;
                int r = id >> 2, c4 = id & 3;
                int gr = rowBase + r;
                aReg[i] = (gr < Nrows)
                    ? *(const float4*)(A + (size_t)gr * K + k0 + c4 * 4)
                    : make_float4(0.f, 0.f, 0.f, 0.f);
                int br = id >> 5, bc4 = id & 31;
                bReg[i] = *(const float4*)(W + (size_t)(k0 + br) * Ncols + colBase + bc4 * 4);
            }
        }

        // compute on current buffer
        #pragma unroll
        for (int kk = 0; kk < 16; kk++) {
            float4 a0 = *(const float4*)&As[buf][kk][ty * 8];
            float4 a1 = *(const float4*)&As[buf][kk][ty * 8 + 4];
            float4 b0 = *(const float4*)&Bs[buf][kk][tx * 8];
            float4 b1 = *(const float4*)&Bs[buf][kk][tx * 8 + 4];
            float a[8] = {a0.x, a0.y, a0.z, a0.w, a1.x, a1.y, a1.z, a1.w};
            float b[8] = {b0.x, b0.y, b0.z, b0.w, b1.x, b1.y, b1.z, b1.w};
            #pragma unroll
            for (int i = 0; i < 8; i++)
                #pragma unroll
                for (int j = 0; j < 8; j++)
                    acc[i][j] = fmaf(a[i], b[j], acc[i][j]);
        }

        if (kt + 1 < KT) {
            int nb = buf ^ 1;
            #pragma unroll
            for (int i = 0; i < 2; i++) {
                int id = tid + i * 256;
                int r = id >> 2, c4 = id & 3;
                As[nb][c4 * 4 + 0][r] = aReg[i].x;
                As[nb][c4 * 4 + 1][r] = aReg[i].y;
                As[nb][c4 * 4 + 2][r] = aReg[i].z;
                As[nb][c4 * 4 + 3][r] = aReg[i].w;
                int br = id >> 5, bc4 = id & 31;
                *(float4*)&Bs[nb][br][bc4 * 4] = bReg[i];
            }
            __syncthreads();
            buf = nb;
        }
    }

    // ---- epilogue: bias + SiLU + store ----
    #pragma unroll
    for (int i = 0; i < 8; i++) {
        int gr = rowBase + ty * 8 + i;
        if (gr >= Nrows) break;
        #pragma unroll
        for (int j = 0; j < 8; j += 4) {
            int gc = colBase + tx * 8 + j;
            float4 v;
            v.x = silu_f(acc[i][j + 0] + bias[gc + 0]);
            v.y = silu_f(acc[i][j + 1] + bias[gc + 1]);
            v.z = silu_f(acc[i][j + 2] + bias[gc + 2]);
            v.w = silu_f(acc[i][j + 3] + bias[gc + 3]);
            *(float4*)(C + (size_t)gr * Ncols + gc) = v;
        }
    }
}

// ---------------------------------------------------------------------------
// Host launcher
// inputs: 0 coords, 1 nodes, 2 comps, 3 aggr_coords, 4 aggr_nodes,
//         5 aggr_comps, 6 ln1_g, 7 ln1_b, 8 W1, 9 b1, 10 ln2_g, 11 ln2_b,
//         12 W2, 13 b2
// ---------------------------------------------------------------------------
extern "C" void kernel_launch(void* const* d_in, const int* in_sizes, int n_in,
                              void* d_out, int out_size) {
    const float* nodes      = (const float*)d_in[1];
    const void*  comps      = d_in[2];
    const float* aggr_nodes = (const float*)d_in[4];
    const void*  aggr_comps = d_in[5];
    const float* ln1_g      = (const float*)d_in[6];
    const float* ln1_b      = (const float*)d_in[7];
    const float* W1         = (const float*)d_in[8];
    const float* b1         = (const float*)d_in[9];
    const float* ln2_g      = (const float*)d_in[10];
    const float* ln2_b      = (const float*)d_in[11];
    const float* W2         = (const float*)d_in[12];
    const float* b2         = (const float*)d_in[13];
    float* out = (float*)d_out;

    int N = in_sizes[1] / FDIM;   // 100000
    int M = in_sizes[4] / FDIM;   // 16384
    if (N > MAX_N) N = MAX_N;

    // 0) detect int32 vs int64 index dtype
    detect_i64_kernel<<<1, 32>>>((const int*)comps);

    // 1) gather + concat + LN1 -> g_X
    gather_ln1_kernel<<<N, 256>>>(nodes, comps, aggr_nodes, aggr_comps,
                                  ln1_g, ln1_b, N, M);

    // 2) GEMM1: g_H = silu(g_X @ W1 + b1)   [N,1024]
    {
        float* Xp; float* Hp;
        cudaGetSymbolAddress((void**)&Xp, g_X);
        cudaGetSymbolAddress((void**)&Hp, g_H);
        dim3 grid(TWOF / 128, (N + 127) / 128);
        gemm_bias_silu_kernel<<<grid, 256>>>(Xp, W1, b1, Hp, N, TWOF);

        // 3) LN2: g_X = LN(g_H)
        ln2_kernel<<<N, 256>>>(ln2_g, ln2_b, N);

        // 4) GEMM2: out = silu(g_X @ W2 + b2)  [N,512]
        dim3 grid2(FDIM / 128, (N + 127) / 128);
        gemm_bias_silu_kernel<<<grid2, 256>>>(Xp, W2, b2, out, N, FDIM);
    }
}

// round 3
// speedup vs baseline: 3.1662x; 3.1662x over previous
#include <cuda_runtime.h>
#include <cstdint>

// ---------------------------------------------------------------------------
// AggregationFusion: gather + concat + LN -> Linear(1024,1024)+SiLU -> LN ->
//                    Linear(1024,512)+SiLU
// N=100000 rows, F=512 (2F=1024), M=16384.
// Round 3: GEMMs on tensor pipe via mma.sync tf32 (m16n8k8) + cp.async.
// ---------------------------------------------------------------------------

#define MAX_N 100000
#define TWOF  1024
#define FDIM  512
#define LN_EPS 1e-5f

__device__ float g_X[(size_t)MAX_N * TWOF];   // LN1 out / LN2 out
__device__ float g_H[(size_t)MAX_N * TWOF];   // GEMM1 out
__device__ int   g_is64;

// ---------------------------------------------------------------------------
__global__ void detect_i64_kernel(const int* __restrict__ comps_words) {
    if (threadIdx.x == 0) {
        int z = 1;
        #pragma unroll
        for (int i = 1; i < 16; i += 2)
            if (comps_words[i] != 0) z = 0;
        g_is64 = z;
    }
}

__device__ __forceinline__ float block_reduce_sum_256(float v, float* sbuf) {
    __syncthreads();
    #pragma unroll
    for (int o = 16; o > 0; o >>= 1) v += __shfl_xor_sync(0xffffffffu, v, o);
    int w = threadIdx.x >> 5, l = threadIdx.x & 31;
    if (l == 0) sbuf[w] = v;
    __syncthreads();
    if (w == 0) {
        v = (l < 8) ? sbuf[l] : 0.0f;
        #pragma unroll
        for (int o = 4; o > 0; o >>= 1) v += __shfl_xor_sync(0xffffffffu, v, o);
        if (l == 0) sbuf[0] = v;
    }
    __syncthreads();
    return sbuf[0];
}

__device__ __forceinline__ float silu_f(float x) {
    return x * (1.0f / (1.0f + __expf(-x)));
}

// ---------------------------------------------------------------------------
// gather + concat + LN1 -> g_X
// ---------------------------------------------------------------------------
__global__ void gather_ln1_kernel(const float* __restrict__ nodes,
                                  const void* __restrict__ comps,
                                  const float* __restrict__ aggr_nodes,
                                  const void* __restrict__ aggr_comps,
                                  const float* __restrict__ ln_g,
                                  const float* __restrict__ ln_b,
                                  int N, int M) {
    int row = blockIdx.x;
    if (row >= N) return;
    int tid = threadIdx.x;
    __shared__ float red[8];
    __shared__ int s_idx;

    if (tid == 0) {
        int is64 = g_is64;
        long long key = is64 ? ((const long long*)comps)[row]
                             : (long long)((const int*)comps)[row];
        int lo = 0, hi = M;
        while (lo < hi) {
            int mid = (lo + hi) >> 1;
            long long am = is64 ? ((const long long*)aggr_comps)[mid]
                                : (long long)((const int*)aggr_comps)[mid];
            if (am < key) lo = mid + 1; else hi = mid;
        }
        if (lo >= M) lo = M - 1;
        s_idx = lo;
    }
    __syncthreads();
    int idx = s_idx;

    float4 v;
    if (tid < 128)
        v = ((const float4*)(nodes + (size_t)row * FDIM))[tid];
    else
        v = ((const float4*)(aggr_nodes + (size_t)idx * FDIM))[tid - 128];

    float sum = v.x + v.y + v.z + v.w;
    sum = block_reduce_sum_256(sum, red);
    float mu = sum * (1.0f / (float)TWOF);

    float dx = v.x - mu, dy = v.y - mu, dz = v.z - mu, dw = v.w - mu;
    float sq = dx * dx + dy * dy + dz * dz + dw * dw;
    sq = block_reduce_sum_256(sq, red);
    float rstd = rsqrtf(sq * (1.0f / (float)TWOF) + LN_EPS);

    float4 gg = ((const float4*)ln_g)[tid];
    float4 bb = ((const float4*)ln_b)[tid];
    float4 o;
    o.x = dx * rstd * gg.x + bb.x;
    o.y = dy * rstd * gg.y + bb.y;
    o.z = dz * rstd * gg.z + bb.z;
    o.w = dw * rstd * gg.w + bb.w;
    ((float4*)(g_X + (size_t)row * TWOF))[tid] = o;
}

// ---------------------------------------------------------------------------
// LN2 over g_H -> g_X
// ---------------------------------------------------------------------------
__global__ void ln2_kernel(const float* __restrict__ ln_g,
                           const float* __restrict__ ln_b,
                           int N) {
    int row = blockIdx.x;
    if (row >= N) return;
    int tid = threadIdx.x;
    __shared__ float red[8];

    float4 v = ((const float4*)(g_H + (size_t)row * TWOF))[tid];
    float sum = v.x + v.y + v.z + v.w;
    sum = block_reduce_sum_256(sum, red);
    float mu = sum * (1.0f / (float)TWOF);

    float dx = v.x - mu, dy = v.y - mu, dz = v.z - mu, dw = v.w - mu;
    float sq = dx * dx + dy * dy + dz * dz + dw * dw;
    sq = block_reduce_sum_256(sq, red);
    float rstd = rsqrtf(sq * (1.0f / (float)TWOF) + LN_EPS);

    float4 gg = ((const float4*)ln_g)[tid];
    float4 bb = ((const float4*)ln_b)[tid];
    float4 o;
    o.x = dx * rstd * gg.x + bb.x;
    o.y = dy * rstd * gg.y + bb.y;
    o.z = dz * rstd * gg.z + bb.z;
    o.w = dw * rstd * gg.w + bb.w;
    ((float4*)(g_X + (size_t)row * TWOF))[tid] = o;
}

// ---------------------------------------------------------------------------
// Tensor-core tf32 GEMM: C = silu(A[Nrows,1024] @ W[1024,Ncols] + bias)
// 128x128x16 tiles, 256 threads, mma.sync m16n8k8 tf32, cp.async 2-stage.
// ---------------------------------------------------------------------------
#define BM 128
#define BN 128
#define BK 16
#define A_STRIDE 20     // floats per As row (pad 4): ldmatrix conflict-free
#define B_STRIDE 136    // floats per Bs row (pad 8): LDS conflict-free

__device__ __forceinline__ void ldm_x4(uint32_t& r0, uint32_t& r1,
                                       uint32_t& r2, uint32_t& r3,
                                       uint32_t addr) {
    asm volatile("ldmatrix.sync.aligned.m8n8.x4.shared.b16 {%0,%1,%2,%3}, [%4];"
                 : "=r"(r0), "=r"(r1), "=r"(r2), "=r"(r3) : "r"(addr));
}

__device__ __forceinline__ void mma_tf32(float& c0, float& c1, float& c2, float& c3,
                                         uint32_t a0, uint32_t a1, uint32_t a2, uint32_t a3,
                                         uint32_t b0, uint32_t b1) {
    asm volatile(
        "mma.sync.aligned.m16n8k8.row.col.f32.tf32.tf32.f32 "
        "{%0,%1,%2,%3}, {%4,%5,%6,%7}, {%8,%9}, {%0,%1,%2,%3};"
        : "+f"(c0), "+f"(c1), "+f"(c2), "+f"(c3)
        : "r"(a0), "r"(a1), "r"(a2), "r"(a3), "r"(b0), "r"(b1));
}

__device__ __forceinline__ void cp_async16(uint32_t dst, const void* src, unsigned pred_sz) {
    asm volatile("cp.async.cg.shared.global [%0], [%1], 16, %2;\n"
                 :: "r"(dst), "l"(src), "r"(pred_sz));
}
__device__ __forceinline__ void cp_commit() {
    asm volatile("cp.async.commit_group;\n");
}
__device__ __forceinline__ void cp_wait0() {
    asm volatile("cp.async.wait_group 0;\n");
}

__global__ __launch_bounds__(256, 2)
void gemm_tf32_bias_silu_kernel(const float* __restrict__ A,
                                const float* __restrict__ W,
                                const float* __restrict__ bias,
                                float* __restrict__ C,
                                int Nrows, int Ncols) {
    const int K = 1024;
    const int KT = K / BK;   // 64

    __shared__ float As[2][BM][A_STRIDE];
    __shared__ float Bs[2][BK][B_STRIDE];

    int tid = threadIdx.x;
    int lane = tid & 31;
    int wid  = tid >> 5;
    int wm = wid >> 2;           // 0..1  warp row
    int wn = wid & 3;            // 0..3  warp col
    int rowBase = blockIdx.y * BM;
    int colBase = blockIdx.x * BN;

    uint32_t as_base = (uint32_t)__cvta_generic_to_shared(&As[0][0][0]);
    uint32_t bs_base = (uint32_t)__cvta_generic_to_shared(&Bs[0][0][0]);

    // --- cp.async source/dest mapping ---
    // A: 128 rows x 16k = 512 float4; thread i handles ids tid, tid+256
    // id -> r = id>>2 (row), c = id&3 (k-float4)
    // B: 16 k x 128 n = 512 float4; id -> kr = id>>5, nc = id&31
    int a_r[2], a_c[2], b_kr[2], b_nc[2];
    uint32_t a_dst[2], b_dst[2];
    unsigned a_sz[2];
    const float* a_srcrow[2];
    #pragma unroll
    for (int i = 0; i < 2; i++) {
        int id = tid + i * 256;
        a_r[i] = id >> 2; a_c[i] = id & 3;
        int gr = rowBase + a_r[i];
        a_sz[i] = (gr < Nrows) ? 16u : 0u;
        int grc = gr < Nrows ? gr : (Nrows - 1);
        a_srcrow[i] = A + (size_t)grc * K + a_c[i] * 4;
        a_dst[i] = as_base + (uint32_t)((a_r[i] * A_STRIDE + a_c[i] * 4) * 4);
        b_kr[i] = id >> 5; b_nc[i] = id & 31;
        b_dst[i] = bs_base + (uint32_t)((b_kr[i] * B_STRIDE + b_nc[i] * 4) * 4);
    }
    const size_t asBufBytes = (size_t)BM * A_STRIDE * 4;
    const size_t bsBufBytes = (size_t)BK * B_STRIDE * 4;

    // zero-fill A pad rows explicitly not needed (cp.async src_size=0 zero-fills)

    // --- ldmatrix lane mapping for A frags ---
    int m_off = lane & 15;
    int k_off = (lane >> 4) * 4;
    // --- B frag lane mapping ---
    int bk = lane & 3;           // k within 4
    int bn = lane >> 2;          // n within 8

    float acc[4][4][4];
    #pragma unroll
    for (int f = 0; f < 4; f++)
        #pragma unroll
        for (int j = 0; j < 4; j++)
            #pragma unroll
            for (int q = 0; q < 4; q++) acc[f][j][q] = 0.0f;

    // ---- prologue: tile 0 into buf 0 ----
    #pragma unroll
    for (int i = 0; i < 2; i++) {
        cp_async16(a_dst[i], a_srcrow[i], a_sz[i]);
        cp_async16(b_dst[i], W + (size_t)b_kr[i] * Ncols + colBase + b_nc[i] * 4, 16u);
    }
    cp_commit();

    int buf = 0;
    for (int kt = 0; kt < KT; kt++) {
        cp_wait0();
        __syncthreads();

        // prefetch next tile into buf^1
        if (kt + 1 < KT) {
            int k0 = (kt + 1) * BK;
            uint32_t aoff = (uint32_t)((buf ^ 1) * asBufBytes);
            uint32_t boff = (uint32_t)((buf ^ 1) * bsBufBytes);
            #pragma unroll
            for (int i = 0; i < 2; i++) {
                cp_async16(a_dst[i] + aoff, a_srcrow[i] + k0, a_sz[i]);
                cp_async16(b_dst[i] + boff,
                           W + (size_t)(k0 + b_kr[i]) * Ncols + colBase + b_nc[i] * 4, 16u);
            }
            cp_commit();
        } else {
            cp_commit();   // keep wait_group semantics uniform
        }

        // compute on buf
        uint32_t asb = as_base + (uint32_t)(buf * asBufBytes);
        uint32_t bsb = bs_base + (uint32_t)(buf * bsBufBytes);
        #pragma unroll
        for (int s = 0; s < 2; s++) {
            // A frags: 4 ldmatrix.x4
            uint32_t a[4][4];
            #pragma unroll
            for (int f = 0; f < 4; f++) {
                uint32_t addr = asb +
                    (uint32_t)(((wm * 64 + f * 16 + m_off) * A_STRIDE + s * 8 + k_off) * 4);
                ldm_x4(a[f][0], a[f][1], a[f][2], a[f][3], addr);
            }
            // B frags: 8 scalar LDS
            uint32_t b[4][2];
            #pragma unroll
            for (int j = 0; j < 4; j++) {
                const float* p0 = (const float*)&Bs[buf][s * 8 + bk][wn * 32 + j * 8 + bn];
                b[j][0] = __float_as_uint(*p0);
                b[j][1] = __float_as_uint(*(p0 + 4 * B_STRIDE));
            }
            #pragma unroll
            for (int f = 0; f < 4; f++)
                #pragma unroll
                for (int j = 0; j < 4; j++)
                    mma_tf32(acc[f][j][0], acc[f][j][1], acc[f][j][2], acc[f][j][3],
                             a[f][0], a[f][1], a[f][2], a[f][3], b[j][0], b[j][1]);
        }
        buf ^= 1;
    }

    // ---- epilogue: bias + SiLU + store ----
    int g = lane >> 2, t = lane & 3;
    #pragma unroll
    for (int f = 0; f < 4; f++) {
        int r0 = rowBase + wm * 64 + f * 16 + g;
        int r1 = r0 + 8;
        #pragma unroll
        for (int j = 0; j < 4; j++) {
            int c = colBase + wn * 32 + j * 8 + 2 * t;
            float bv0 = bias[c], bv1 = bias[c + 1];
            if (r0 < Nrows) {
                float2 v;
                v.x = silu_f(acc[f][j][0] + bv0);
                v.y = silu_f(acc[f][j][1] + bv1);
                *(float2*)(C + (size_t)r0 * Ncols + c) = v;
            }
            if (r1 < Nrows) {
                float2 v;
                v.x = silu_f(acc[f][j][2] + bv0);
                v.y = silu_f(acc[f][j][3] + bv1);
                *(float2*)(C + (size_t)r1 * Ncols + c) = v;
            }
        }
    }
}

// ---------------------------------------------------------------------------
extern "C" void kernel_launch(void* const* d_in, const int* in_sizes, int n_in,
                              void* d_out, int out_size) {
    const float* nodes      = (const float*)d_in[1];
    const void*  comps      = d_in[2];
    const float* aggr_nodes = (const float*)d_in[4];
    const void*  aggr_comps = d_in[5];
    const float* ln1_g      = (const float*)d_in[6];
    const float* ln1_b      = (const float*)d_in[7];
    const float* W1         = (const float*)d_in[8];
    const float* b1         = (const float*)d_in[9];
    const float* ln2_g      = (const float*)d_in[10];
    const float* ln2_b      = (const float*)d_in[11];
    const float* W2         = (const float*)d_in[12];
    const float* b2         = (const float*)d_in[13];
    float* out = (float*)d_out;

    int N = in_sizes[1] / FDIM;   // 100000
    int M = in_sizes[4] / FDIM;   // 16384
    if (N > MAX_N) N = MAX_N;

    detect_i64_kernel<<<1, 32>>>((const int*)comps);

    gather_ln1_kernel<<<N, 256>>>(nodes, comps, aggr_nodes, aggr_comps,
                                  ln1_g, ln1_b, N, M);

    float* Xp; float* Hp;
    cudaGetSymbolAddress((void**)&Xp, g_X);
    cudaGetSymbolAddress((void**)&Hp, g_H);

    dim3 grid1(TWOF / BN, (N + BM - 1) / BM);
    gemm_tf32_bias_silu_kernel<<<grid1, 256>>>(Xp, W1, b1, Hp, N, TWOF);

    ln2_kernel<<<N, 256>>>(ln2_g, ln2_b, N);

    dim3 grid2(FDIM / BN, (N + BM - 1) / BM);
    gemm_tf32_bias_silu_kernel<<<grid2, 256>>>(Xp, W2, b2, out, N, FDIM);
}

// round 5
// speedup vs baseline: 4.4874x; 1.4173x over previous
#include <cuda_runtime.h>
#include <cuda_fp16.h>
#include <cstdint>

// ---------------------------------------------------------------------------
// AggregationFusion (sm_103 base-ISA tensor path):
//  gather+concat+LN1 (fp32 -> fp16 RN) -> GEMM1 fp16 HMMA m16n8k16 + SiLU (fp32)
//  -> LN2 -> GEMM2 + SiLU -> out
// tcgen05 unavailable (harness PTX targets sm_103, not sm_103a).
// ---------------------------------------------------------------------------

#define MAX_N 100000
#define TWOF  1024
#define FDIM  512
#define LN_EPS 1e-5f

__device__ float   g_H[(size_t)MAX_N * TWOF];      // GEMM1 out (fp32)
__device__ __half  g_Xh[(size_t)MAX_N * TWOF];     // LN1/LN2 out (fp16)
__device__ __half  g_Wt1[(size_t)TWOF * TWOF];     // W1^T [n][k]
__device__ __half  g_Wt2[(size_t)FDIM * TWOF];     // W2^T [n][k]
__device__ int     g_is64;

// ---------------------------------------------------------------------------
__global__ void detect_i64_kernel(const int* __restrict__ comps_words) {
    if (threadIdx.x == 0) {
        int z = 1;
        #pragma unroll
        for (int i = 1; i < 16; i += 2)
            if (comps_words[i] != 0) z = 0;
        g_is64 = z;
    }
}

__device__ __forceinline__ float block_reduce_sum_256(float v, float* sbuf) {
    __syncthreads();
    #pragma unroll
    for (int o = 16; o > 0; o >>= 1) v += __shfl_xor_sync(0xffffffffu, v, o);
    int w = threadIdx.x >> 5, l = threadIdx.x & 31;
    if (l == 0) sbuf[w] = v;
    __syncthreads();
    if (w == 0) {
        v = (l < 8) ? sbuf[l] : 0.0f;
        #pragma unroll
        for (int o = 4; o > 0; o >>= 1) v += __shfl_xor_sync(0xffffffffu, v, o);
        if (l == 0) sbuf[0] = v;
    }
    __syncthreads();
    return sbuf[0];
}

__device__ __forceinline__ float silu_f(float x) {
    return x * (1.0f / (1.0f + __expf(-x)));
}

// ---------------------------------------------------------------------------
// gather + concat + LN1 -> g_Xh (fp16 RN)
// ---------------------------------------------------------------------------
__global__ void gather_ln1_kernel(const float* __restrict__ nodes,
                                  const void* __restrict__ comps,
                                  const float* __restrict__ aggr_nodes,
                                  const void* __restrict__ aggr_comps,
                                  const float* __restrict__ ln_g,
                                  const float* __restrict__ ln_b,
                                  int N, int M) {
    int row = blockIdx.x;
    if (row >= N) return;
    int tid = threadIdx.x;
    __shared__ float red[8];
    __shared__ int s_idx;

    if (tid == 0) {
        int is64 = g_is64;
        long long key = is64 ? ((const long long*)comps)[row]
                             : (long long)((const int*)comps)[row];
        int lo = 0, hi = M;
        while (lo < hi) {
            int mid = (lo + hi) >> 1;
            long long am = is64 ? ((const long long*)aggr_comps)[mid]
                                : (long long)((const int*)aggr_comps)[mid];
            if (am < key) lo = mid + 1; else hi = mid;
        }
        if (lo >= M) lo = M - 1;
        s_idx = lo;
    }
    __syncthreads();
    int idx = s_idx;

    float4 v;
    if (tid < 128)
        v = ((const float4*)(nodes + (size_t)row * FDIM))[tid];
    else
        v = ((const float4*)(aggr_nodes + (size_t)idx * FDIM))[tid - 128];

    float sum = v.x + v.y + v.z + v.w;
    sum = block_reduce_sum_256(sum, red);
    float mu = sum * (1.0f / (float)TWOF);

    float dx = v.x - mu, dy = v.y - mu, dz = v.z - mu, dw = v.w - mu;
    float sq = dx * dx + dy * dy + dz * dz + dw * dw;
    sq = block_reduce_sum_256(sq, red);
    float rstd = rsqrtf(sq * (1.0f / (float)TWOF) + LN_EPS);

    float4 gg = ((const float4*)ln_g)[tid];
    float4 bb = ((const float4*)ln_b)[tid];
    __half2* dst = (__half2*)(g_Xh + (size_t)row * TWOF + tid * 4);
    dst[0] = __floats2half2_rn(dx * rstd * gg.x + bb.x, dy * rstd * gg.y + bb.y);
    dst[1] = __floats2half2_rn(dz * rstd * gg.z + bb.z, dw * rstd * gg.w + bb.w);
}

// ---------------------------------------------------------------------------
// LN2 over g_H -> g_Xh
// ---------------------------------------------------------------------------
__global__ void ln2_kernel(const float* __restrict__ ln_g,
                           const float* __restrict__ ln_b,
                           int N) {
    int row = blockIdx.x;
    if (row >= N) return;
    int tid = threadIdx.x;
    __shared__ float red[8];

    float4 v = ((const float4*)(g_H + (size_t)row * TWOF))[tid];
    float sum = v.x + v.y + v.z + v.w;
    sum = block_reduce_sum_256(sum, red);
    float mu = sum * (1.0f / (float)TWOF);

    float dx = v.x - mu, dy = v.y - mu, dz = v.z - mu, dw = v.w - mu;
    float sq = dx * dx + dy * dy + dz * dz + dw * dw;
    sq = block_reduce_sum_256(sq, red);
    float rstd = rsqrtf(sq * (1.0f / (float)TWOF) + LN_EPS);

    float4 gg = ((const float4*)ln_g)[tid];
    float4 bb = ((const float4*)ln_b)[tid];
    __half2* dst = (__half2*)(g_Xh + (size_t)row * TWOF + tid * 4);
    dst[0] = __floats2half2_rn(dx * rstd * gg.x + bb.x, dy * rstd * gg.y + bb.y);
    dst[1] = __floats2half2_rn(dz * rstd * gg.z + bb.z, dw * rstd * gg.w + bb.w);
}

// ---------------------------------------------------------------------------
// W transpose + fp16: W[K][Ncols] -> Wt[Ncols][K] fp16   (K=1024)
// ---------------------------------------------------------------------------
__global__ void wprep_kernel(const float* __restrict__ W,
                             __half* __restrict__ T,
                             int Ncols) {
    __shared__ float t[32][33];
    int bx = blockIdx.x * 32;   // n
    int by = blockIdx.y * 32;   // k
    int tx = threadIdx.x, ty = threadIdx.y;
    #pragma unroll
    for (int i = 0; i < 32; i += 8)
        t[ty + i][tx] = W[(size_t)(by + ty + i) * Ncols + bx + tx];
    __syncthreads();
    #pragma unroll
    for (int i = 0; i < 32; i += 8) {
        int n = bx + ty + i, k = by + tx;
        T[(size_t)n * TWOF + k] = __float2half_rn(t[tx][ty + i]);
    }
}

// ---------------------------------------------------------------------------
// fp16 HMMA GEMM: C = silu(A[Nrows,1024] @ W[1024,Ncols] + bias)
// A fp16 [m][k], Wt fp16 [n][k]. CTA 128x128, BK=32 (halves), 256 thr,
// warp tile 64x32 (2x4 warps), mma m16n8k16, double-buffered cp.async.
// smem row stride 40 halves (80B): conflict-free ldmatrix phases.
// ---------------------------------------------------------------------------
#define BM 128
#define BN 128
#define BKH 32          // k-halves per stage
#define AST 40          // halves per smem row (32 + 8 pad)

__device__ __forceinline__ uint32_t smem_u32(const void* p) {
    uint32_t a;
    asm("{ .reg .u64 t; cvta.to.shared.u64 t, %1; cvt.u32.u64 %0, t; }"
        : "=r"(a) : "l"(p));
    return a;
}
__device__ __forceinline__ void ldm_x4(uint32_t& r0, uint32_t& r1,
                                       uint32_t& r2, uint32_t& r3, uint32_t addr) {
    asm volatile("ldmatrix.sync.aligned.m8n8.x4.shared.b16 {%0,%1,%2,%3}, [%4];"
                 : "=r"(r0), "=r"(r1), "=r"(r2), "=r"(r3) : "r"(addr));
}
__device__ __forceinline__ void ldm_x2(uint32_t& r0, uint32_t& r1, uint32_t addr) {
    asm volatile("ldmatrix.sync.aligned.m8n8.x2.shared.b16 {%0,%1}, [%2];"
                 : "=r"(r0), "=r"(r1) : "r"(addr));
}
__device__ __forceinline__ void mma_f16(float& c0, float& c1, float& c2, float& c3,
                                        uint32_t a0, uint32_t a1, uint32_t a2, uint32_t a3,
                                        uint32_t b0, uint32_t b1) {
    asm volatile(
        "mma.sync.aligned.m16n8k16.row.col.f32.f16.f16.f32 "
        "{%0,%1,%2,%3}, {%4,%5,%6,%7}, {%8,%9}, {%0,%1,%2,%3};"
        : "+f"(c0), "+f"(c1), "+f"(c2), "+f"(c3)
        : "r"(a0), "r"(a1), "r"(a2), "r"(a3), "r"(b0), "r"(b1));
}
__device__ __forceinline__ void cp_async16(uint32_t dst, const void* src, unsigned sz) {
    asm volatile("cp.async.cg.shared.global [%0], [%1], 16, %2;\n"
                 :: "r"(dst), "l"(src), "r"(sz));
}
__device__ __forceinline__ void cp_commit() { asm volatile("cp.async.commit_group;\n"); }
__device__ __forceinline__ void cp_wait0()  { asm volatile("cp.async.wait_group 0;\n"); }

__global__ __launch_bounds__(256, 2)
void gemm_f16_bias_silu_kernel(const __half* __restrict__ A,
                               const __half* __restrict__ Wt,
                               const float* __restrict__ bias,
                               float* __restrict__ C,
                               int Nrows, int Ncols) {
    const int K = TWOF;
    const int KT = K / BKH;       // 32

    __shared__ __half As[2][BM][AST];
    __shared__ __half Bs[2][BN][AST];

    int tid = threadIdx.x;
    int lane = tid & 31;
    int wid  = tid >> 5;
    int wm = wid >> 2;            // 0..1
    int wn = wid & 3;             // 0..3
    int rowBase = blockIdx.y * BM;
    int colBase = blockIdx.x * BN;

    // ---- cp.async mapping: thread -> row tid>>1, two 16B segs ----
    int r  = tid >> 1;
    int sg = (tid & 1) * 2;       // segments sg, sg+1 (16B each)
    int gA = rowBase + r;
    bool a_ok = gA < Nrows;
    unsigned asz = a_ok ? 16u : 0u;
    const char* a_src = (const char*)(A + (size_t)(a_ok ? gA : 0) * K);
    const char* b_src = (const char*)(Wt + (size_t)(colBase + r) * K);
    uint32_t a_dst0 = smem_u32(&As[0][r][sg * 8]);
    uint32_t b_dst0 = smem_u32(&Bs[0][r][sg * 8]);
    const uint32_t aBuf = (uint32_t)(BM * AST * 2);   // bytes per buffer

    auto load_tile = [&](int buf, int kt) {
        const char* sa = a_src + kt * (BKH * 2);
        const char* sb = b_src + kt * (BKH * 2);
        uint32_t da = a_dst0 + buf * aBuf;
        uint32_t db = b_dst0 + buf * aBuf;
        #pragma unroll
        for (int i = 0; i < 2; i++) {
            cp_async16(da + i * 16, sa + (sg + i) * 16, asz);
            cp_async16(db + i * 16, sb + (sg + i) * 16, 16u);
        }
        cp_commit();
    };

    // ---- frag addresses ----
    // A (x4): row = wm*64 + f*16 + (lane&15), col halves = ks*16 + (lane>>4)*8
    // B (x2): n  = wn*32 + j*8 + (lane&7),  col halves = ks*16 + ((lane>>3)&1)*8
    int aRow = (lane & 15);
    int aCol = (lane >> 4) * 8;
    int bRow = (lane & 7);
    int bCol = ((lane >> 3) & 1) * 8;

    float acc[4][4][4];
    #pragma unroll
    for (int f = 0; f < 4; f++)
        #pragma unroll
        for (int j = 0; j < 4; j++)
            #pragma unroll
            for (int q = 0; q < 4; q++) acc[f][j][q] = 0.0f;

    load_tile(0, 0);

    int buf = 0;
    for (int kt = 0; kt < KT; kt++) {
        cp_wait0();
        __syncthreads();

        if (kt + 1 < KT) load_tile(buf ^ 1, kt + 1);

        #pragma unroll
        for (int ks = 0; ks < 2; ks++) {
            uint32_t a[4][4];
            #pragma unroll
            for (int f = 0; f < 4; f++) {
                uint32_t addr = smem_u32(
                    &As[buf][wm * 64 + f * 16 + aRow][ks * 16 + aCol]);
                ldm_x4(a[f][0], a[f][1], a[f][2], a[f][3], addr);
            }
            uint32_t b[4][2];
            #pragma unroll
            for (int j = 0; j < 4; j++) {
                uint32_t addr = smem_u32(
                    &Bs[buf][wn * 32 + j * 8 + bRow][ks * 16 + bCol]);
                ldm_x2(b[j][0], b[j][1], addr);
            }
            #pragma unroll
            for (int f = 0; f < 4; f++)
                #pragma unroll
                for (int j = 0; j < 4; j++)
                    mma_f16(acc[f][j][0], acc[f][j][1], acc[f][j][2], acc[f][j][3],
                            a[f][0], a[f][1], a[f][2], a[f][3], b[j][0], b[j][1]);
        }
        buf ^= 1;
    }

    // ---- epilogue: bias + SiLU + store fp32 ----
    int g = lane >> 2, t = lane & 3;
    #pragma unroll
    for (int f = 0; f < 4; f++) {
        int r0 = rowBase + wm * 64 + f * 16 + g;
        int r1 = r0 + 8;
        #pragma unroll
        for (int j = 0; j < 4; j++) {
            int c = colBase + wn * 32 + j * 8 + 2 * t;
            float bv0 = bias[c], bv1 = bias[c + 1];
            if (r0 < Nrows) {
                float2 v;
                v.x = silu_f(acc[f][j][0] + bv0);
                v.y = silu_f(acc[f][j][1] + bv1);
                *(float2*)(C + (size_t)r0 * Ncols + c) = v;
            }
            if (r1 < Nrows) {
                float2 v;
                v.x = silu_f(acc[f][j][2] + bv0);
                v.y = silu_f(acc[f][j][3] + bv1);
                *(float2*)(C + (size_t)r1 * Ncols + c) = v;
            }
        }
    }
}

// ---------------------------------------------------------------------------
extern "C" void kernel_launch(void* const* d_in, const int* in_sizes, int n_in,
                              void* d_out, int out_size) {
    const float* nodes      = (const float*)d_in[1];
    const void*  comps      = d_in[2];
    const float* aggr_nodes = (const float*)d_in[4];
    const void*  aggr_comps = d_in[5];
    const float* ln1_g      = (const float*)d_in[6];
    const float* ln1_b      = (const float*)d_in[7];
    const float* W1         = (const float*)d_in[8];
    const float* b1         = (const float*)d_in[9];
    const float* ln2_g      = (const float*)d_in[10];
    const float* ln2_b      = (const float*)d_in[11];
    const float* W2         = (const float*)d_in[12];
    const float* b2         = (const float*)d_in[13];
    float* out = (float*)d_out;

    int N = in_sizes[1] / FDIM;   // 100000
    int M = in_sizes[4] / FDIM;   // 16384
    if (N > MAX_N) N = MAX_N;

    __half *Xh, *Wt1, *Wt2;
    float* Hp;
    cudaGetSymbolAddress((void**)&Xh,  g_Xh);
    cudaGetSymbolAddress((void**)&Wt1, g_Wt1);
    cudaGetSymbolAddress((void**)&Wt2, g_Wt2);
    cudaGetSymbolAddress((void**)&Hp,  g_H);

    detect_i64_kernel<<<1, 32>>>((const int*)comps);

    {
        dim3 b(32, 8);
        wprep_kernel<<<dim3(TWOF / 32, TWOF / 32), b>>>(W1, Wt1, TWOF);
        wprep_kernel<<<dim3(FDIM / 32, TWOF / 32), b>>>(W2, Wt2, FDIM);
    }

    gather_ln1_kernel<<<N, 256>>>(nodes, comps, aggr_nodes, aggr_comps,
                                  ln1_g, ln1_b, N, M);

    int rowTiles = (N + BM - 1) / BM;
    dim3 grid1(TWOF / BN, rowTiles);
    gemm_f16_bias_silu_kernel<<<grid1, 256>>>(Xh, Wt1, b1, Hp, N, TWOF);

    ln2_kernel<<<N, 256>>>(ln2_g, ln2_b, N);

    dim3 grid2(FDIM / BN, rowTiles);
    gemm_f16_bias_silu_kernel<<<grid2, 256>>>(Xh, Wt2, b2, out, N, FDIM);
}

// round 6
// speedup vs baseline: 5.3378x; 1.1895x over previous
#include <cuda_runtime.h>
#include <cuda_fp16.h>
#include <cstdint>

// ---------------------------------------------------------------------------
// AggregationFusion (sm_103 base-ISA tensor path):
//  gather+concat+LN1 (warp-per-row, fp32 -> fp16 RN) -> GEMM1 fp16 HMMA + SiLU
//  -> LN2 (warp-per-row) -> GEMM2 + SiLU -> out
// GEMM: 128x128 CTA tile, 3-stage cp.async pipeline, m16n8k16 fp16/f32-acc.
// ---------------------------------------------------------------------------

#define MAX_N 100000
#define TWOF  1024
#define FDIM  512
#define LN_EPS 1e-5f

__device__ float   g_H[(size_t)MAX_N * TWOF];      // GEMM1 out (fp32)
__device__ __half  g_Xh[(size_t)MAX_N * TWOF];     // LN1/LN2 out (fp16)
__device__ __half  g_Wt1[(size_t)TWOF * TWOF];     // W1^T [n][k]
__device__ __half  g_Wt2[(size_t)FDIM * TWOF];     // W2^T [n][k]
__device__ int     g_is64;

// ---------------------------------------------------------------------------
__global__ void detect_i64_kernel(const int* __restrict__ comps_words) {
    if (threadIdx.x == 0) {
        int z = 1;
        #pragma unroll
        for (int i = 1; i < 16; i += 2)
            if (comps_words[i] != 0) z = 0;
        g_is64 = z;
    }
}

__device__ __forceinline__ float warp_sum(float v) {
    #pragma unroll
    for (int o = 16; o > 0; o >>= 1) v += __shfl_xor_sync(0xffffffffu, v, o);
    return v;
}

__device__ __forceinline__ float silu_f(float x) {
    return x * (1.0f / (1.0f + __expf(-x)));
}

// ---------------------------------------------------------------------------
// gather + concat + LN1 (warp per row) -> g_Xh
// ---------------------------------------------------------------------------
__global__ __launch_bounds__(256)
void gather_ln1_kernel(const float* __restrict__ nodes,
                       const void* __restrict__ comps,
                       const float* __restrict__ aggr_nodes,
                       const void* __restrict__ aggr_comps,
                       const float* __restrict__ ln_g,
                       const float* __restrict__ ln_b,
                       int N, int M) {
    int row = blockIdx.x * 8 + (threadIdx.x >> 5);
    if (row >= N) return;
    int lane = threadIdx.x & 31;

    int idx = 0;
    if (lane == 0) {
        int is64 = g_is64;
        long long key = is64 ? ((const long long*)comps)[row]
                             : (long long)((const int*)comps)[row];
        int lo = 0, hi = M;
        while (lo < hi) {
            int mid = (lo + hi) >> 1;
            long long am = is64 ? ((const long long*)aggr_comps)[mid]
                                : (long long)((const int*)aggr_comps)[mid];
            if (am < key) lo = mid + 1; else hi = mid;
        }
        idx = (lo >= M) ? (M - 1) : lo;
    }
    idx = __shfl_sync(0xffffffffu, idx, 0);

    const float4* s1 = (const float4*)(nodes + (size_t)row * FDIM);
    const float4* s2 = (const float4*)(aggr_nodes + (size_t)idx * FDIM);
    float4 v[8];
    #pragma unroll
    for (int i = 0; i < 4; i++) v[i]     = s1[i * 32 + lane];
    #pragma unroll
    for (int i = 0; i < 4; i++) v[4 + i] = s2[i * 32 + lane];

    float sum = 0.0f;
    #pragma unroll
    for (int i = 0; i < 8; i++) sum += v[i].x + v[i].y + v[i].z + v[i].w;
    float mu = warp_sum(sum) * (1.0f / (float)TWOF);

    float sq = 0.0f;
    #pragma unroll
    for (int i = 0; i < 8; i++) {
        float a = v[i].x - mu, b = v[i].y - mu, c = v[i].z - mu, d = v[i].w - mu;
        sq += a * a + b * b + c * c + d * d;
    }
    float rstd = rsqrtf(warp_sum(sq) * (1.0f / (float)TWOF) + LN_EPS);

    uint2* dst = (uint2*)(g_Xh + (size_t)row * TWOF);
    #pragma unroll
    for (int i = 0; i < 8; i++) {
        int slot = i * 32 + lane;            // float4 slot in row
        float4 gg = ((const float4*)ln_g)[slot];
        float4 bb = ((const float4*)ln_b)[slot];
        __half2 h0 = __floats2half2_rn((v[i].x - mu) * rstd * gg.x + bb.x,
                                       (v[i].y - mu) * rstd * gg.y + bb.y);
        __half2 h1 = __floats2half2_rn((v[i].z - mu) * rstd * gg.z + bb.z,
                                       (v[i].w - mu) * rstd * gg.w + bb.w);
        uint2 p;
        p.x = *(uint32_t*)&h0;
        p.y = *(uint32_t*)&h1;
        dst[slot] = p;
    }
}

// ---------------------------------------------------------------------------
// LN2 (warp per row) over g_H -> g_Xh
// ---------------------------------------------------------------------------
__global__ __launch_bounds__(256)
void ln2_kernel(const float* __restrict__ ln_g,
                const float* __restrict__ ln_b,
                int N) {
    int row = blockIdx.x * 8 + (threadIdx.x >> 5);
    if (row >= N) return;
    int lane = threadIdx.x & 31;

    const float4* src = (const float4*)(g_H + (size_t)row * TWOF);
    float4 v[8];
    #pragma unroll
    for (int i = 0; i < 8; i++) v[i] = src[i * 32 + lane];

    float sum = 0.0f;
    #pragma unroll
    for (int i = 0; i < 8; i++) sum += v[i].x + v[i].y + v[i].z + v[i].w;
    float mu = warp_sum(sum) * (1.0f / (float)TWOF);

    float sq = 0.0f;
    #pragma unroll
    for (int i = 0; i < 8; i++) {
        float a = v[i].x - mu, b = v[i].y - mu, c = v[i].z - mu, d = v[i].w - mu;
        sq += a * a + b * b + c * c + d * d;
    }
    float rstd = rsqrtf(warp_sum(sq) * (1.0f / (float)TWOF) + LN_EPS);

    uint2* dst = (uint2*)(g_Xh + (size_t)row * TWOF);
    #pragma unroll
    for (int i = 0; i < 8; i++) {
        int slot = i * 32 + lane;
        float4 gg = ((const float4*)ln_g)[slot];
        float4 bb = ((const float4*)ln_b)[slot];
        __half2 h0 = __floats2half2_rn((v[i].x - mu) * rstd * gg.x + bb.x,
                                       (v[i].y - mu) * rstd * gg.y + bb.y);
        __half2 h1 = __floats2half2_rn((v[i].z - mu) * rstd * gg.z + bb.z,
                                       (v[i].w - mu) * rstd * gg.w + bb.w);
        uint2 p;
        p.x = *(uint32_t*)&h0;
        p.y = *(uint32_t*)&h1;
        dst[slot] = p;
    }
}

// ---------------------------------------------------------------------------
// W transpose + fp16: W[K][Ncols] -> Wt[Ncols][K]
// ---------------------------------------------------------------------------
__global__ void wprep_kernel(const float* __restrict__ W,
                             __half* __restrict__ T,
                             int Ncols) {
    __shared__ float t[32][33];
    int bx = blockIdx.x * 32;   // n
    int by = blockIdx.y * 32;   // k
    int tx = threadIdx.x, ty = threadIdx.y;
    #pragma unroll
    for (int i = 0; i < 32; i += 8)
        t[ty + i][tx] = W[(size_t)(by + ty + i) * Ncols + bx + tx];
    __syncthreads();
    #pragma unroll
    for (int i = 0; i < 32; i += 8) {
        int n = bx + ty + i, k = by + tx;
        T[(size_t)n * TWOF + k] = __float2half_rn(t[tx][ty + i]);
    }
}

// ---------------------------------------------------------------------------
// fp16 HMMA GEMM, 3-stage cp.async pipeline.
// ---------------------------------------------------------------------------
#define BM 128
#define BN 128
#define BKH 32          // k-halves per stage
#define AST 40          // halves per smem row (32 + 8 pad)
#define NST 3
#define TILE_HALVES (BM * AST)                 // per matrix per stage
#define STAGE_BYTES (TILE_HALVES * 2 * 2)      // A + B, bytes

__device__ __forceinline__ uint32_t smem_u32(const void* p) {
    uint32_t a;
    asm("{ .reg .u64 t; cvta.to.shared.u64 t, %1; cvt.u32.u64 %0, t; }"
        : "=r"(a) : "l"(p));
    return a;
}
__device__ __forceinline__ void ldm_x4(uint32_t& r0, uint32_t& r1,
                                       uint32_t& r2, uint32_t& r3, uint32_t addr) {
    asm volatile("ldmatrix.sync.aligned.m8n8.x4.shared.b16 {%0,%1,%2,%3}, [%4];"
                 : "=r"(r0), "=r"(r1), "=r"(r2), "=r"(r3) : "r"(addr));
}
__device__ __forceinline__ void ldm_x2(uint32_t& r0, uint32_t& r1, uint32_t addr) {
    asm volatile("ldmatrix.sync.aligned.m8n8.x2.shared.b16 {%0,%1}, [%2];"
                 : "=r"(r0), "=r"(r1) : "r"(addr));
}
__device__ __forceinline__ void mma_f16(float& c0, float& c1, float& c2, float& c3,
                                        uint32_t a0, uint32_t a1, uint32_t a2, uint32_t a3,
                                        uint32_t b0, uint32_t b1) {
    asm volatile(
        "mma.sync.aligned.m16n8k16.row.col.f32.f16.f16.f32 "
        "{%0,%1,%2,%3}, {%4,%5,%6,%7}, {%8,%9}, {%0,%1,%2,%3};"
        : "+f"(c0), "+f"(c1), "+f"(c2), "+f"(c3)
        : "r"(a0), "r"(a1), "r"(a2), "r"(a3), "r"(b0), "r"(b1));
}
__device__ __forceinline__ void cp_async16(uint32_t dst, const void* src, unsigned sz) {
    asm volatile("cp.async.cg.shared.global [%0], [%1], 16, %2;\n"
                 :: "r"(dst), "l"(src), "r"(sz));
}
__device__ __forceinline__ void cp_commit() { asm volatile("cp.async.commit_group;\n"); }
__device__ __forceinline__ void cp_wait0()  { asm volatile("cp.async.wait_group 0;\n"); }
__device__ __forceinline__ void cp_wait1()  { asm volatile("cp.async.wait_group 1;\n"); }

extern __shared__ __half sm_gemm[];

__global__ __launch_bounds__(256, 2)
void gemm_f16_bias_silu_kernel(const __half* __restrict__ A,
                               const __half* __restrict__ Wt,
                               const float* __restrict__ bias,
                               float* __restrict__ C,
                               int Nrows, int Ncols) {
    const int K = TWOF;
    const int KT = K / BKH;       // 32

    // dyn smem: As[NST][BM][AST] then Bs[NST][BM][AST]
    __half* AsBase = sm_gemm;
    __half* BsBase = sm_gemm + (size_t)NST * TILE_HALVES;

    int tid = threadIdx.x;
    int lane = tid & 31;
    int wid  = tid >> 5;
    int wm = wid >> 2;            // 0..1
    int wn = wid & 3;             // 0..3
    int rowBase = blockIdx.y * BM;
    int colBase = blockIdx.x * BN;

    // ---- cp.async mapping: thread -> row tid>>1, two 16B segs ----
    int r  = tid >> 1;
    int sg = (tid & 1) * 2;
    int gA = rowBase + r;
    bool a_ok = gA < Nrows;
    unsigned asz = a_ok ? 16u : 0u;
    const char* a_src = (const char*)(A + (size_t)(a_ok ? gA : 0) * K);
    const char* b_src = (const char*)(Wt + (size_t)(colBase + r) * K);
    uint32_t a_dst0 = smem_u32(AsBase + r * AST + sg * 8);
    uint32_t b_dst0 = smem_u32(BsBase + r * AST + sg * 8);
    const uint32_t stB = (uint32_t)(TILE_HALVES * 2);   // bytes per stage per matrix

    auto load_tile = [&](int st, int kt) {
        const char* sa = a_src + kt * (BKH * 2);
        const char* sb = b_src + kt * (BKH * 2);
        uint32_t da = a_dst0 + st * stB;
        uint32_t db = b_dst0 + st * stB;
        #pragma unroll
        for (int i = 0; i < 2; i++) {
            cp_async16(da + i * 16, sa + (sg + i) * 16, asz);
            cp_async16(db + i * 16, sb + (sg + i) * 16, 16u);
        }
        cp_commit();
    };

    int aRow = (lane & 15);
    int aCol = (lane >> 4) * 8;
    int bRow = (lane & 7);
    int bCol = ((lane >> 3) & 1) * 8;

    float acc[4][4][4];
    #pragma unroll
    for (int f = 0; f < 4; f++)
        #pragma unroll
        for (int j = 0; j < 4; j++)
            #pragma unroll
            for (int q = 0; q < 4; q++) acc[f][j][q] = 0.0f;

    load_tile(0, 0);
    load_tile(1, 1);

    for (int kt = 0; kt < KT; kt++) {
        int st = kt % NST;
        if (kt + 1 < KT) cp_wait1(); else cp_wait0();
        __syncthreads();

        if (kt + 2 < KT) load_tile((kt + 2) % NST, kt + 2);

        __half* Asb = AsBase + (size_t)st * TILE_HALVES;
        __half* Bsb = BsBase + (size_t)st * TILE_HALVES;

        #pragma unroll
        for (int ks = 0; ks < 2; ks++) {
            uint32_t a[4][4];
            #pragma unroll
            for (int f = 0; f < 4; f++) {
                uint32_t addr = smem_u32(
                    Asb + (wm * 64 + f * 16 + aRow) * AST + ks * 16 + aCol);
                ldm_x4(a[f][0], a[f][1], a[f][2], a[f][3], addr);
            }
            uint32_t b[4][2];
            #pragma unroll
            for (int j = 0; j < 4; j++) {
                uint32_t addr = smem_u32(
                    Bsb + (wn * 32 + j * 8 + bRow) * AST + ks * 16 + bCol);
                ldm_x2(b[j][0], b[j][1], addr);
            }
            #pragma unroll
            for (int f = 0; f < 4; f++)
                #pragma unroll
                for (int j = 0; j < 4; j++)
                    mma_f16(acc[f][j][0], acc[f][j][1], acc[f][j][2], acc[f][j][3],
                            a[f][0], a[f][1], a[f][2], a[f][3], b[j][0], b[j][1]);
        }
    }

    // ---- epilogue: bias + SiLU + store fp32 ----
    int g = lane >> 2, t = lane & 3;
    #pragma unroll
    for (int f = 0; f < 4; f++) {
        int r0 = rowBase + wm * 64 + f * 16 + g;
        int r1 = r0 + 8;
        #pragma unroll
        for (int j = 0; j < 4; j++) {
            int c = colBase + wn * 32 + j * 8 + 2 * t;
            float bv0 = __ldg(&bias[c]), bv1 = __ldg(&bias[c + 1]);
            if (r0 < Nrows) {
                float2 v;
                v.x = silu_f(acc[f][j][0] + bv0);
                v.y = silu_f(acc[f][j][1] + bv1);
                *(float2*)(C + (size_t)r0 * Ncols + c) = v;
            }
            if (r1 < Nrows) {
                float2 v;
                v.x = silu_f(acc[f][j][2] + bv0);
                v.y = silu_f(acc[f][j][3] + bv1);
                *(float2*)(C + (size_t)r1 * Ncols + c) = v;
            }
        }
    }
}

// ---------------------------------------------------------------------------
extern "C" void kernel_launch(void* const* d_in, const int* in_sizes, int n_in,
                              void* d_out, int out_size) {
    const float* nodes      = (const float*)d_in[1];
    const void*  comps      = d_in[2];
    const float* aggr_nodes = (const float*)d_in[4];
    const void*  aggr_comps = d_in[5];
    const float* ln1_g      = (const float*)d_in[6];
    const float* ln1_b      = (const float*)d_in[7];
    const float* W1         = (const float*)d_in[8];
    const float* b1         = (const float*)d_in[9];
    const float* ln2_g      = (const float*)d_in[10];
    const float* ln2_b      = (const float*)d_in[11];
    const float* W2         = (const float*)d_in[12];
    const float* b2         = (const float*)d_in[13];
    float* out = (float*)d_out;

    int N = in_sizes[1] / FDIM;   // 100000
    int M = in_sizes[4] / FDIM;   // 16384
    if (N > MAX_N) N = MAX_N;

    const int gemm_smem = NST * STAGE_BYTES;   // 61440
    cudaFuncSetAttribute(gemm_f16_bias_silu_kernel,
                         cudaFuncAttributeMaxDynamicSharedMemorySize, gemm_smem);

    __half *Xh, *Wt1, *Wt2;
    float* Hp;
    cudaGetSymbolAddress((void**)&Xh,  g_Xh);
    cudaGetSymbolAddress((void**)&Wt1, g_Wt1);
    cudaGetSymbolAddress((void**)&Wt2, g_Wt2);
    cudaGetSymbolAddress((void**)&Hp,  g_H);

    detect_i64_kernel<<<1, 32>>>((const int*)comps);

    {
        dim3 b(32, 8);
        wprep_kernel<<<dim3(TWOF / 32, TWOF / 32), b>>>(W1, Wt1, TWOF);
        wprep_kernel<<<dim3(FDIM / 32, TWOF / 32), b>>>(W2, Wt2, FDIM);
    }

    gather_ln1_kernel<<<(N + 7) / 8, 256>>>(nodes, comps, aggr_nodes, aggr_comps,
                                            ln1_g, ln1_b, N, M);

    int rowTiles = (N + BM - 1) / BM;
    dim3 grid1(TWOF / BN, rowTiles);
    gemm_f16_bias_silu_kernel<<<grid1, 256, gemm_smem>>>(Xh, Wt1, b1, Hp, N, TWOF);

    ln2_kernel<<<(N + 7) / 8, 256>>>(ln2_g, ln2_b, N);

    dim3 grid2(FDIM / BN, rowTiles);
    gemm_f16_bias_silu_kernel<<<grid2, 256, gemm_smem>>>(Xh, Wt2, b2, out, N, FDIM);
}